// round 1
// baseline (speedup 1.0000x reference)
#include <cuda_runtime.h>
#include <cstdint>

#define BSZ 2
#define LEN 2048
#define NHD 24
#define DH  64
#define DS  128

#define NPAIR   (BSZ*NHD)      // 48
#define DSPLIT  2
#define DLOC    (DH/DSPLIT)    // 32
#define THREADS 256
#define DEPTH   6
#define NBUF    (DEPTH+1)      // 7

// ---------------- scratch (no allocation allowed) ----------------
__device__ float g_abar[BSZ*LEN*NHD + 8];

// ---------------- a_bar precompute ----------------
__global__ void abar_kernel(const float* __restrict__ A,
                            const float* __restrict__ dp) {
    int i = blockIdx.x * blockDim.x + threadIdx.x;
    const int n = BSZ * LEN * NHD;
    if (i < n) {
        float a  = A[i];
        float v  = a + dp[i % NHD];
        float sp = (v > 20.f) ? v : log1pf(expf(v));   // stable softplus
        g_abar[i] = expf(-sp * fabsf(a));
    }
}

// ---------------- cp.async helpers ----------------
__device__ __forceinline__ unsigned smem_u32(const void* p) {
    return (unsigned)__cvta_generic_to_shared(p);
}
__device__ __forceinline__ void cpa16(unsigned dst, const float* src) {
    asm volatile("cp.async.cg.shared.global [%0], [%1], 16;\n"
                 :: "r"(dst), "l"(src));
}
__device__ __forceinline__ void cpa4(unsigned dst, const float* src) {
    asm volatile("cp.async.ca.shared.global [%0], [%1], 4;\n"
                 :: "r"(dst), "l"(src));
}
__device__ __forceinline__ void cp_commit() {
    asm volatile("cp.async.commit_group;\n" ::: "memory");
}

// ---------------- per-step staging tile ----------------
struct Tile {
    float4 Bs[DS/4];    // 32 x 16B = 512B  (full 128 B_t values)
    float4 Cs[DS/4];    // 512B             (full 128 C_t values)
    float4 xs[DLOC/4];  // 128B             (this block's 32 x_t values)
    float  a;           // a_bar_t
    float  pad3[3];
};

// ---------------- main sequential-scan kernel ----------------
__global__ __launch_bounds__(THREADS, 1)
void ssm_kernel(const float* __restrict__ x,
                const float* __restrict__ Bm,
                const float* __restrict__ Cm,
                float* __restrict__ out) {
    __shared__ Tile tiles[NBUF];

    const int tid   = threadIdx.x;
    const int bx    = blockIdx.x;
    const int pair  = bx >> 1;          // (b, h) pair
    const int dpart = bx & 1;           // which DH half
    const int b     = pair / NHD;
    const int hh    = pair % NHD;

    const int d_loc = tid >> 3;         // 0..31 (output row within half)
    const int q     = tid & 7;          // 0..7  (16 ds-columns each)

    const size_t pairbase = (size_t)(b * LEN) * NHD + hh;  // +t*NHD per step

    // one cp.async role per thread (73 active lanes: 32 B, 32 C, 8 x, 1 a)
    auto issue = [&](int t, int buf) {
        size_t base = pairbase + (size_t)t * NHD;
        Tile& T = tiles[buf];
        if (tid < 32) {
            cpa16(smem_u32(&T.Bs[tid]),      Bm + base * DS + tid * 4);
        } else if (tid < 64) {
            cpa16(smem_u32(&T.Cs[tid - 32]), Cm + base * DS + (tid - 32) * 4);
        } else if (tid < 72) {
            cpa16(smem_u32(&T.xs[tid - 64]),
                  x + base * DH + dpart * DLOC + (tid - 64) * 4);
        } else if (tid == 72) {
            cpa4(smem_u32(&T.a), g_abar + base);
        }
    };

    // prologue: fill DEPTH stages
    #pragma unroll
    for (int t = 0; t < DEPTH; ++t) { issue(t, t); cp_commit(); }

    float h[16];
    #pragma unroll
    for (int j = 0; j < 16; ++j) h[j] = 0.f;

    int cur = 0, nxt = DEPTH;
    const size_t outbase = pairbase * DH + dpart * DLOC + d_loc;

    for (int t = 0; t < LEN; ++t) {
        // stage t arrived?  (<= DEPTH-1 groups pending)
        asm volatile("cp.async.wait_group 5;\n" ::: "memory");
        __syncthreads();

        const Tile& T = tiles[cur];
        const float a  = T.a;
        const float xv = ((const float*)T.xs)[d_loc];
        float y = 0.f;

        #pragma unroll
        for (int j = 0; j < 4; ++j) {
            float4 Bv = T.Bs[q * 4 + j];
            float4 Cv = T.Cs[q * 4 + j];
            h[4*j+0] = a * h[4*j+0] + xv * Bv.x;  y += h[4*j+0] * Cv.x;
            h[4*j+1] = a * h[4*j+1] + xv * Bv.y;  y += h[4*j+1] * Cv.y;
            h[4*j+2] = a * h[4*j+2] + xv * Bv.z;  y += h[4*j+2] * Cv.z;
            h[4*j+3] = a * h[4*j+3] + xv * Bv.w;  y += h[4*j+3] * Cv.w;
        }

        // reduce y over the 8 lanes sharing this d
        y += __shfl_down_sync(0xffffffffu, y, 4, 8);
        y += __shfl_down_sync(0xffffffffu, y, 2, 8);
        y += __shfl_down_sync(0xffffffffu, y, 1, 8);
        if (q == 0) out[outbase + (size_t)t * (NHD * DH)] = y;

        // refill ring for step t+DEPTH (buffer (t-1)%7, safe after barrier)
        int tn = t + DEPTH;
        if (tn < LEN) issue(tn, nxt);
        cp_commit();   // always commit (possibly-empty group) to keep counts uniform

        if (++cur == NBUF) cur = 0;
        if (++nxt == NBUF) nxt = 0;
    }
}

// ---------------- launch ----------------
extern "C" void kernel_launch(void* const* d_in, const int* in_sizes, int n_in,
                              void* d_out, int out_size) {
    const float* x  = (const float*)d_in[0];
    const float* A  = (const float*)d_in[1];
    const float* Bm = (const float*)d_in[2];
    const float* Cm = (const float*)d_in[3];
    const float* dp = (const float*)d_in[4];
    (void)in_sizes; (void)n_in; (void)out_size;

    const int n = BSZ * LEN * NHD;
    abar_kernel<<<(n + 255) / 256, 256>>>(A, dp);
    ssm_kernel<<<NPAIR * DSPLIT, THREADS>>>(x, Bm, Cm, (float*)d_out);
}

// round 2
// speedup vs baseline: 1.0830x; 1.0830x over previous
#include <cuda_runtime.h>
#include <cstdint>

#define BSZ 2
#define LEN 2048
#define NHD 24
#define DH  64
#define DS  128

#define NPAIR (BSZ*NHD)     // 48
#define TC    64            // chunk length
#define NCH   (LEN/TC)      // 32
#define THREADS 256

#define BP  132             // padded row stride for 128-wide rows (floats)
#define BP4 (BP/4)          // 33
#define XP  68              // padded row stride for 64-wide rows
#define XP4 (XP/4)          // 17

// ------------- device scratch (no allocation allowed) -------------
__device__ float g_la[BSZ*LEN*NHD];                 // log(a_bar), <= 0
__device__ float g_S [NPAIR*NCH*DH*DS];             // 50 MB chunk contributions
__device__ float g_H [NPAIR*NCH*DH*DS];             // 50 MB chunk-start states
__device__ float g_P [NPAIR*NCH];                   // chunk decay products

// ------------- log(a_bar) precompute -------------
__global__ void la_kernel(const float* __restrict__ A,
                          const float* __restrict__ dp) {
    int i = blockIdx.x * blockDim.x + threadIdx.x;
    const int n = BSZ * LEN * NHD;
    if (i < n) {
        float a  = A[i];
        float v  = a + dp[i % NHD];
        float sp = (v > 20.f) ? v : log1pf(expf(v));   // stable softplus
        g_la[i]  = -sp * fabsf(a);                     // log(a_bar) <= 0
    }
}

// =================================================================
// Pass 1: per (pair, chunk) compute S_j[d,s] = sum_t w_t x_t[d] B_t[s]
//         with w_t = exp(lcp_end - lcp_t), and P_j = exp(lcp_end).
// =================================================================
__global__ __launch_bounds__(THREADS, 1)
void pass1_kernel(const float* __restrict__ x,
                  const float* __restrict__ Bm) {
    extern __shared__ float sm[];
    float* Bsh = sm;                       // TC x BP
    float* xsh = Bsh + TC*BP;              // TC x XP
    float* lcp = xsh + TC*XP;              // TC
    float* lw  = lcp + TC;                 // TC

    const int tid  = threadIdx.x;
    const int ch   = blockIdx.x;
    const int pair = blockIdx.y;
    const int b    = pair / NHD;
    const int hh   = pair % NHD;
    const int t0   = ch * TC;

    // --- load log-decays, inclusive scan ---
    if (tid < TC) lcp[tid] = g_la[((size_t)b*LEN + t0 + tid)*NHD + hh];
    __syncthreads();
    if (tid == 0) {
        float s = 0.f;
        #pragma unroll 8
        for (int t = 0; t < TC; ++t) { s += lcp[t]; lcp[t] = s; }
    }
    __syncthreads();
    if (tid < TC) lw[tid] = expf(lcp[TC-1] - lcp[tid]);
    if (tid == 0) g_P[pair*NCH + ch] = expf(lcp[TC-1]);

    // --- stage B (TC x DS) and x (TC x DH) ---
    for (int i = tid; i < TC*(DS/4); i += THREADS) {
        int t = i >> 5, c = i & 31;
        const float4 v = ((const float4*)(Bm + (((size_t)b*LEN + t0+t)*NHD + hh)*DS))[c];
        ((float4*)(Bsh + t*BP))[c] = v;
    }
    for (int i = tid; i < TC*(DH/4); i += THREADS) {
        int t = i >> 4, c = i & 15;
        const float4 v = ((const float4*)(x + (((size_t)b*LEN + t0+t)*NHD + hh)*DH))[c];
        ((float4*)(xsh + t*XP))[c] = v;
    }
    __syncthreads();

    // --- accumulate S: thread (d, sg) owns 32 s-columns ---
    const int d  = tid >> 2;       // 0..63
    const int sg = tid & 3;        // 0..3
    float4 acc[8];
    #pragma unroll
    for (int j = 0; j < 8; ++j) acc[j] = make_float4(0.f,0.f,0.f,0.f);

    for (int t = 0; t < TC; ++t) {
        const float xw = xsh[t*XP + d] * lw[t];
        const float4* Brow = (const float4*)(Bsh + t*BP) + sg*8;
        #pragma unroll
        for (int j = 0; j < 8; ++j) {
            float4 b4 = Brow[j];
            acc[j].x += xw * b4.x; acc[j].y += xw * b4.y;
            acc[j].z += xw * b4.z; acc[j].w += xw * b4.w;
        }
    }

    float* Sdst = g_S + ((size_t)(pair*NCH + ch))*DH*DS + d*DS + sg*32;
    #pragma unroll
    for (int j = 0; j < 8; ++j) ((float4*)Sdst)[j] = acc[j];
}

// =================================================================
// Pass 2: per pair, serial scan over chunks: store H_j, then
//         H_{j+1} = P_j * H_j + S_j   (elementwise over 64x128)
// =================================================================
__global__ __launch_bounds__(THREADS, 1)
void pass2_kernel() {
    const int pair = blockIdx.x;
    const int tid  = threadIdx.x;
    float4 Hr[8];
    #pragma unroll
    for (int j = 0; j < 8; ++j) Hr[j] = make_float4(0.f,0.f,0.f,0.f);

    for (int ch = 0; ch < NCH; ++ch) {
        const size_t base = ((size_t)(pair*NCH + ch))*DH*DS;
        float4* Hd = (float4*)(g_H + base);
        const float4* Sd = (const float4*)(g_S + base);
        #pragma unroll
        for (int j = 0; j < 8; ++j) Hd[tid + j*THREADS] = Hr[j];
        const float P = g_P[pair*NCH + ch];
        #pragma unroll
        for (int j = 0; j < 8; ++j) {
            float4 s4 = Sd[tid + j*THREADS];
            Hr[j].x = P*Hr[j].x + s4.x; Hr[j].y = P*Hr[j].y + s4.y;
            Hr[j].z = P*Hr[j].z + s4.z; Hr[j].w = P*Hr[j].w + s4.w;
        }
    }
}

// =================================================================
// Pass 3: per (pair, chunk):
//   W[t,s] = (s<=t) ? exp(lcp_t - lcp_s) * (B_s . C_t) : 0
//   y[t,d] = exp(lcp_t) * (H_j C_t)[d] + sum_s W[t,s] x_s[d]
// =================================================================
__global__ __launch_bounds__(THREADS, 1)
void pass3_kernel(const float* __restrict__ x,
                  const float* __restrict__ Bm,
                  const float* __restrict__ Cm,
                  float* __restrict__ out) {
    extern __shared__ float sm[];
    float* Csh = sm;                        // TC x BP
    float* Bsh = Csh + TC*BP;               // TC x BP
    float* Hsh = Bsh + TC*BP;               // DH x BP
    float* xsh = Hsh + TC*BP;               // TC x XP
    float* Wsh = xsh + TC*XP;               // TC x XP
    float* lcp = Wsh + TC*XP;               // TC
    float* elc = lcp + TC;                  // TC

    const int tid  = threadIdx.x;
    const int ch   = blockIdx.x;
    const int pair = blockIdx.y;
    const int b    = pair / NHD;
    const int hh   = pair % NHD;
    const int t0   = ch * TC;

    if (tid < TC) lcp[tid] = g_la[((size_t)b*LEN + t0 + tid)*NHD + hh];
    __syncthreads();
    if (tid == 0) {
        float s = 0.f;
        #pragma unroll 8
        for (int t = 0; t < TC; ++t) { s += lcp[t]; lcp[t] = s; }
    }
    __syncthreads();
    if (tid < TC) elc[tid] = expf(lcp[tid]);

    // stage C, B (TC x DS), H (DH x DS), x (TC x DH)
    const size_t rowbase = ((size_t)b*LEN + t0)*NHD + hh;
    for (int i = tid; i < TC*(DS/4); i += THREADS) {
        int t = i >> 5, c = i & 31;
        ((float4*)(Csh + t*BP))[c] = ((const float4*)(Cm + (rowbase + (size_t)t*NHD)*DS))[c];
        ((float4*)(Bsh + t*BP))[c] = ((const float4*)(Bm + (rowbase + (size_t)t*NHD)*DS))[c];
    }
    const float* Hsrc = g_H + ((size_t)(pair*NCH + ch))*DH*DS;
    for (int i = tid; i < DH*(DS/4); i += THREADS) {
        int d = i >> 5, c = i & 31;
        ((float4*)(Hsh + d*BP))[c] = ((const float4*)Hsrc)[i];
    }
    for (int i = tid; i < TC*(DH/4); i += THREADS) {
        int t = i >> 4, c = i & 15;
        ((float4*)(xsh + t*XP))[c] = ((const float4*)(x + (rowbase + (size_t)t*NHD)*DH))[c];
    }
    __syncthreads();

    const int t  = tid >> 2;     // 0..63
    const int qg = tid & 3;      // 0..3

    // --- phase W: G[t,s] for s in [qg*16, qg*16+16) ---
    {
        float acc[16];
        #pragma unroll
        for (int k = 0; k < 16; ++k) acc[k] = 0.f;
        const float4* Crow = (const float4*)(Csh + t*BP);
        for (int i4 = 0; i4 < DS/4; ++i4) {
            const float4 c4 = Crow[i4];
            #pragma unroll
            for (int k = 0; k < 16; ++k) {
                float4 b4 = ((const float4*)(Bsh + (qg*16 + k)*BP))[i4];
                acc[k] += c4.x*b4.x + c4.y*b4.y + c4.z*b4.z + c4.w*b4.w;
            }
        }
        const float lt = lcp[t];
        #pragma unroll
        for (int k = 0; k < 16; ++k) {
            int s = qg*16 + k;
            Wsh[t*XP + s] = (s <= t) ? expf(lt - lcp[s]) * acc[k] : 0.f;
        }
    }
    __syncthreads();

    // --- phase M + y: d in [qg*16, qg*16+16) ---
    {
        float yv[16];
        #pragma unroll
        for (int k = 0; k < 16; ++k) yv[k] = 0.f;
        const float4* Crow = (const float4*)(Csh + t*BP);
        for (int i4 = 0; i4 < DS/4; ++i4) {
            const float4 c4 = Crow[i4];
            #pragma unroll
            for (int k = 0; k < 16; ++k) {
                float4 h4 = ((const float4*)(Hsh + (qg*16 + k)*BP))[i4];
                yv[k] += c4.x*h4.x + c4.y*h4.y + c4.z*h4.z + c4.w*h4.w;
            }
        }
        const float et = elc[t];
        #pragma unroll
        for (int k = 0; k < 16; ++k) yv[k] *= et;

        for (int s = 0; s <= t; ++s) {            // causal: W is 0 beyond t
            const float w = Wsh[t*XP + s];
            const float4* xrow = (const float4*)(xsh + s*XP) + qg*4;
            #pragma unroll
            for (int j = 0; j < 4; ++j) {
                float4 x4 = xrow[j];
                yv[j*4+0] += w * x4.x; yv[j*4+1] += w * x4.y;
                yv[j*4+2] += w * x4.z; yv[j*4+3] += w * x4.w;
            }
        }

        float* yout = out + (rowbase + (size_t)t*NHD)*DH + qg*16;
        #pragma unroll
        for (int j = 0; j < 4; ++j)
            ((float4*)yout)[j] = make_float4(yv[j*4+0], yv[j*4+1], yv[j*4+2], yv[j*4+3]);
    }
}

// ------------- launch -------------
extern "C" void kernel_launch(void* const* d_in, const int* in_sizes, int n_in,
                              void* d_out, int out_size) {
    const float* x  = (const float*)d_in[0];
    const float* A  = (const float*)d_in[1];
    const float* Bm = (const float*)d_in[2];
    const float* Cm = (const float*)d_in[3];
    const float* dp = (const float*)d_in[4];
    (void)in_sizes; (void)n_in; (void)out_size;

    const int smem1 = (TC*BP + TC*XP + 2*TC) * sizeof(float);          // ~51.5 KB
    const int smem3 = (3*TC*BP + 2*TC*XP + 2*TC) * sizeof(float);      // ~136.7 KB
    cudaFuncSetAttribute(pass1_kernel, cudaFuncAttributeMaxDynamicSharedMemorySize, smem1);
    cudaFuncSetAttribute(pass3_kernel, cudaFuncAttributeMaxDynamicSharedMemorySize, smem3);

    const int n = BSZ * LEN * NHD;
    la_kernel<<<(n + 255) / 256, 256>>>(A, dp);
    dim3 grid(NCH, NPAIR);
    pass1_kernel<<<grid, THREADS, smem1>>>(x, Bm);
    pass2_kernel<<<NPAIR, THREADS>>>();
    pass3_kernel<<<grid, THREADS, smem3>>>(x, Bm, Cm, (float*)d_out);
}

// round 3
// speedup vs baseline: 3.7225x; 3.4373x over previous
#include <cuda_runtime.h>
#include <cstdint>

#define BSZ 2
#define LEN 2048
#define NHD 24
#define DH  64
#define DS  128

#define NPAIR (BSZ*NHD)     // 48
#define TC    64            // chunk length
#define NCH   (LEN/TC)      // 32
#define THREADS 256

#define XPITCH 68           // pitch for 64-wide rows (floats)

// ------------- device scratch (no allocation allowed) -------------
__device__ float g_la[BSZ*LEN*NHD];        // log(a_bar) <= 0
__device__ float g_S [NPAIR*NCH*DH*DS];    // chunk contributions
__device__ float g_H [NPAIR*NCH*DH*DS];    // chunk-start states
__device__ float g_P [NPAIR*NCH];          // chunk decay products

// smem swizzle: physical float4-col = logical-col ^ sw(row)
__device__ __forceinline__ int swz(int r) { return ((r >> 3) ^ r) & 7; }

// ------------- log(a_bar) precompute -------------
__global__ void la_kernel(const float* __restrict__ A,
                          const float* __restrict__ dp) {
    int i = blockIdx.x * blockDim.x + threadIdx.x;
    const int n = BSZ * LEN * NHD;
    if (i < n) {
        float a  = A[i];
        float v  = a + dp[i % NHD];
        float sp = (v > 20.f) ? v : log1pf(expf(v));
        g_la[i]  = -sp * fabsf(a);
    }
}

// parallel inclusive scan of lcp[0..TC) in smem (all threads call)
__device__ __forceinline__ void scan_lcp(float* lcp, int tid) {
    for (int off = 1; off < TC; off <<= 1) {
        float v = 0.f;
        if (tid < TC && tid >= off) v = lcp[tid - off];
        __syncthreads();
        if (tid < TC) lcp[tid] += v;
        __syncthreads();
    }
}

// =================================================================
// Pass 1: S_j[d,s] = sum_t w_t x[t,d] B[t,s],  w_t = exp(lcp_end - lcp_t)
// Register-blocked GEMM, output 64x128, k = t = 64.
// =================================================================
__global__ __launch_bounds__(THREADS, 1)
void pass1_kernel(const float* __restrict__ x,
                  const float* __restrict__ Bm) {
    extern __shared__ float sm[];
    float*  Bsh  = sm;                    // 64 x 128, swizzled
    float*  xsh  = Bsh + TC * DS;         // 64 x XPITCH
    float*  lcp  = xsh + TC * XPITCH;     // TC
    float*  lw   = lcp + TC;              // TC
    float4* Bsh4 = (float4*)Bsh;

    const int tid  = threadIdx.x;
    const int ch   = blockIdx.x;
    const int pair = blockIdx.y;
    const int b    = pair / NHD;
    const int hh   = pair % NHD;
    const size_t rowbase = ((size_t)b * LEN + ch * TC) * NHD + hh;

    for (int i = tid; i < TC * (DS/4); i += THREADS) {
        int t = i >> 5, c = i & 31;
        float4 v = ((const float4*)(Bm + (rowbase + (size_t)t*NHD) * DS))[c];
        Bsh4[t * 32 + (c ^ swz(t))] = v;
    }
    for (int i = tid; i < TC * (DH/4); i += THREADS) {
        int t = i >> 4, c = i & 15;
        ((float4*)(xsh + t * XPITCH))[c] =
            ((const float4*)(x + (rowbase + (size_t)t*NHD) * DH))[c];
    }
    if (tid < TC) lcp[tid] = g_la[rowbase + (size_t)tid * NHD];
    __syncthreads();
    scan_lcp(lcp, tid);
    if (tid < TC) lw[tid] = expf(lcp[TC-1] - lcp[tid]);
    if (tid == 0) g_P[pair*NCH + ch] = expf(lcp[TC-1]);
    __syncthreads();
    for (int i = tid; i < TC * DH; i += THREADS) {       // scale x by w_t
        int t = i >> 6, d = i & 63;
        xsh[t * XPITCH + d] *= lw[t];
    }
    __syncthreads();

    const int ty = tid >> 4, tx = tid & 15;   // thread tile: 4 d x 8 s
    float acc[4][8];
    #pragma unroll
    for (int i = 0; i < 4; ++i)
        #pragma unroll
        for (int j = 0; j < 8; ++j) acc[i][j] = 0.f;

    #pragma unroll 4
    for (int t = 0; t < TC; ++t) {
        const int s = swz(t);
        float4 xv = *(const float4*)(xsh + t * XPITCH + 4 * ty);
        float4 b0 = Bsh4[t * 32 + ((2*tx)   ^ s)];
        float4 b1 = Bsh4[t * 32 + ((2*tx+1) ^ s)];
        float xx[4] = {xv.x, xv.y, xv.z, xv.w};
        float bb[8] = {b0.x, b0.y, b0.z, b0.w, b1.x, b1.y, b1.z, b1.w};
        #pragma unroll
        for (int i = 0; i < 4; ++i)
            #pragma unroll
            for (int j = 0; j < 8; ++j) acc[i][j] += xx[i] * bb[j];
    }

    float* Sdst = g_S + ((size_t)(pair*NCH + ch)) * DH * DS;
    #pragma unroll
    for (int i = 0; i < 4; ++i) {
        float* p = Sdst + (4*ty + i) * DS + 8*tx;
        ((float4*)p)[0] = make_float4(acc[i][0], acc[i][1], acc[i][2], acc[i][3]);
        ((float4*)p)[1] = make_float4(acc[i][4], acc[i][5], acc[i][6], acc[i][7]);
    }
}

// =================================================================
// Pass 2: per pair serial chunk scan:  H_j stored, H_{j+1} = P_j H_j + S_j
// =================================================================
__global__ __launch_bounds__(THREADS, 1)
void pass2_kernel() {
    const int pair = blockIdx.x;
    const int tid  = threadIdx.x;
    float4 Hr[8];
    #pragma unroll
    for (int j = 0; j < 8; ++j) Hr[j] = make_float4(0.f, 0.f, 0.f, 0.f);

    for (int ch = 0; ch < NCH; ++ch) {
        const size_t base = ((size_t)(pair*NCH + ch)) * DH * DS;
        float4* Hd = (float4*)(g_H + base);
        const float4* Sd = (const float4*)(g_S + base);
        #pragma unroll
        for (int j = 0; j < 8; ++j) Hd[tid + j*THREADS] = Hr[j];
        const float P = g_P[pair*NCH + ch];
        #pragma unroll
        for (int j = 0; j < 8; ++j) {
            float4 s4 = Sd[tid + j*THREADS];
            Hr[j].x = P*Hr[j].x + s4.x;  Hr[j].y = P*Hr[j].y + s4.y;
            Hr[j].z = P*Hr[j].z + s4.z;  Hr[j].w = P*Hr[j].w + s4.w;
        }
    }
}

// =================================================================
// Pass 3:  R[64x128] = C(64x128) . D(128x128)^T  with D = [B ; H]
//   cols j<64:  W[t,s] = mask * exp(lcp_t - lcp_s) * R
//   cols j>=64: Y1[t,d] = exp(lcp_t) * R
// then Y = Y1 + W . x   (causal), written to out.
// =================================================================
__global__ __launch_bounds__(THREADS, 1)
void pass3_kernel(const float* __restrict__ x,
                  const float* __restrict__ Bm,
                  const float* __restrict__ Cm,
                  float* __restrict__ out) {
    extern __shared__ float sm[];
    float*  Csh  = sm;                        // 64 x 128, swizzled
    float*  Dsh  = Csh + TC * DS;             // 128 x 128, swizzled
    float*  xsh  = Dsh + 2 * TC * DS;         // 64 x XPITCH
    float*  Wsh  = xsh + TC * XPITCH;         // 64 x XPITCH
    float*  Ysh  = Wsh + TC * XPITCH;         // 64 x XPITCH
    float*  lcp  = Ysh + TC * XPITCH;         // TC
    float*  elc  = lcp + TC;                  // TC
    float4* Csh4 = (float4*)Csh;
    float4* Dsh4 = (float4*)Dsh;

    const int tid  = threadIdx.x;
    const int ch   = blockIdx.x;
    const int pair = blockIdx.y;
    const int b    = pair / NHD;
    const int hh   = pair % NHD;
    const size_t rowbase = ((size_t)b * LEN + ch * TC) * NHD + hh;

    for (int i = tid; i < TC * (DS/4); i += THREADS) {
        int t = i >> 5, c = i & 31;
        Csh4[t * 32 + (c ^ swz(t))] =
            ((const float4*)(Cm + (rowbase + (size_t)t*NHD) * DS))[c];
        Dsh4[t * 32 + (c ^ swz(t))] =
            ((const float4*)(Bm + (rowbase + (size_t)t*NHD) * DS))[c];
    }
    const float4* Hsrc = (const float4*)(g_H + ((size_t)(pair*NCH + ch)) * DH * DS);
    for (int i = tid; i < DH * (DS/4); i += THREADS) {
        int d = i >> 5, c = i & 31;
        int r = 64 + d;
        Dsh4[r * 32 + (c ^ swz(r))] = Hsrc[i];
    }
    for (int i = tid; i < TC * (DH/4); i += THREADS) {
        int t = i >> 4, c = i & 15;
        ((float4*)(xsh + t * XPITCH))[c] =
            ((const float4*)(x + (rowbase + (size_t)t*NHD) * DH))[c];
    }
    if (tid < TC) lcp[tid] = g_la[rowbase + (size_t)tid * NHD];
    __syncthreads();
    scan_lcp(lcp, tid);
    if (tid < TC) elc[tid] = expf(lcp[tid]);
    __syncthreads();

    // ---------------- GEMM1: 4t x 8j per thread, k = 128 ----------------
    const int ty = tid >> 4, tx = tid & 15;
    int swc[4], swd[8];
    #pragma unroll
    for (int i = 0; i < 4; ++i) swc[i] = swz(4*ty + i);
    #pragma unroll
    for (int j = 0; j < 8; ++j) swd[j] = swz(8*tx + j);

    float acc[4][8];
    #pragma unroll
    for (int i = 0; i < 4; ++i)
        #pragma unroll
        for (int j = 0; j < 8; ++j) acc[i][j] = 0.f;

    #pragma unroll 2
    for (int c = 0; c < 32; ++c) {
        float4 Cf[4], Df[8];
        #pragma unroll
        for (int i = 0; i < 4; ++i) Cf[i] = Csh4[(4*ty + i) * 32 + (c ^ swc[i])];
        #pragma unroll
        for (int j = 0; j < 8; ++j) Df[j] = Dsh4[(8*tx + j) * 32 + (c ^ swd[j])];
        #pragma unroll
        for (int i = 0; i < 4; ++i)
            #pragma unroll
            for (int j = 0; j < 8; ++j) {
                acc[i][j] += Cf[i].x * Df[j].x;
                acc[i][j] += Cf[i].y * Df[j].y;
                acc[i][j] += Cf[i].z * Df[j].z;
                acc[i][j] += Cf[i].w * Df[j].w;
            }
    }

    // ---------------- epilogue: split into W (masked) and Y1 ----------------
    if (tx < 8) {
        #pragma unroll
        for (int i = 0; i < 4; ++i) {
            int t = 4*ty + i;
            float lt = lcp[t];
            #pragma unroll
            for (int j = 0; j < 8; ++j) {
                int s = 8*tx + j;
                Wsh[t * XPITCH + s] = (s <= t) ? expf(lt - lcp[s]) * acc[i][j] : 0.f;
            }
        }
    } else {
        #pragma unroll
        for (int i = 0; i < 4; ++i) {
            int t = 4*ty + i;
            float et = elc[t];
            #pragma unroll
            for (int j = 0; j < 8; ++j)
                Ysh[t * XPITCH + 8*(tx - 8) + j] = et * acc[i][j];
        }
    }
    __syncthreads();

    // ---------------- GEMM2: Y += W . x, 4t x 4d per thread, causal ----------------
    float yacc[4][4];
    #pragma unroll
    for (int i = 0; i < 4; ++i) {
        float4 yv = *(const float4*)(Ysh + (4*ty + i) * XPITCH + 4*tx);
        yacc[i][0] = yv.x; yacc[i][1] = yv.y; yacc[i][2] = yv.z; yacc[i][3] = yv.w;
    }
    for (int s4 = 0; s4 <= ty; ++s4) {      // s in [0, 4*ty+4): covers s <= t
        float4 Wf[4], xf[4];
        #pragma unroll
        for (int i = 0; i < 4; ++i)
            Wf[i] = *(const float4*)(Wsh + (4*ty + i) * XPITCH + 4*s4);
        #pragma unroll
        for (int k = 0; k < 4; ++k)
            xf[k] = *(const float4*)(xsh + (4*s4 + k) * XPITCH + 4*tx);
        #pragma unroll
        for (int i = 0; i < 4; ++i) {
            float w0 = Wf[i].x, w1 = Wf[i].y, w2 = Wf[i].z, w3 = Wf[i].w;
            yacc[i][0] += w0*xf[0].x + w1*xf[1].x + w2*xf[2].x + w3*xf[3].x;
            yacc[i][1] += w0*xf[0].y + w1*xf[1].y + w2*xf[2].y + w3*xf[3].y;
            yacc[i][2] += w0*xf[0].z + w1*xf[1].z + w2*xf[2].z + w3*xf[3].z;
            yacc[i][3] += w0*xf[0].w + w1*xf[1].w + w2*xf[2].w + w3*xf[3].w;
        }
    }
    #pragma unroll
    for (int i = 0; i < 4; ++i) {
        float* yout = out + (rowbase + (size_t)(4*ty + i) * NHD) * DH + 4*tx;
        *(float4*)yout = make_float4(yacc[i][0], yacc[i][1], yacc[i][2], yacc[i][3]);
    }
}

// ------------- launch -------------
extern "C" void kernel_launch(void* const* d_in, const int* in_sizes, int n_in,
                              void* d_out, int out_size) {
    const float* x  = (const float*)d_in[0];
    const float* A  = (const float*)d_in[1];
    const float* Bm = (const float*)d_in[2];
    const float* Cm = (const float*)d_in[3];
    const float* dp = (const float*)d_in[4];
    (void)in_sizes; (void)n_in; (void)out_size;

    const int smem1 = (TC*DS + TC*XPITCH + 2*TC) * sizeof(float);           // ~50.7 KB
    const int smem3 = (3*TC*DS + 3*TC*XPITCH + 2*TC) * sizeof(float);       // ~151 KB
    cudaFuncSetAttribute(pass1_kernel, cudaFuncAttributeMaxDynamicSharedMemorySize, smem1);
    cudaFuncSetAttribute(pass3_kernel, cudaFuncAttributeMaxDynamicSharedMemorySize, smem3);

    const int n = BSZ * LEN * NHD;
    la_kernel<<<(n + 255) / 256, 256>>>(A, dp);
    dim3 grid(NCH, NPAIR);
    pass1_kernel<<<grid, THREADS, smem1>>>(x, Bm);
    pass2_kernel<<<NPAIR, THREADS>>>();
    pass3_kernel<<<grid, THREADS, smem3>>>(x, Bm, Cm, (float*)d_out);
}